// round 1
// baseline (speedup 1.0000x reference)
#include <cuda_runtime.h>
#include <math.h>

#define BATCH 256
#define SEQ   512
#define ISZ   256
#define HSZ   512
#define G4    2048   // 4*HSZ, gate-interleaved: col j = u*4 + g, g in {i,f,g,o}

// ---------------- device scratch (allocation-free) ----------------
__device__ float g_xu[(size_t)SEQ * BATCH * G4];  // 1 GiB: xu[t][b][j]
__device__ float g_wu[ISZ * G4];                  // packed W_u  [I][4H interleaved]
__device__ float g_wh[HSZ * G4];                  // packed W_h  [H][4H interleaved]
__device__ float g_bias[G4];
__device__ float g_h[2][BATCH * HSZ];             // double-buffered hidden state
__device__ float g_c[BATCH * HSZ];

// ---------------- pack weights into gate-interleaved layout + init state ----
__global__ void pack_kernel(const float* __restrict__ Wui, const float* __restrict__ Whi, const float* __restrict__ bi,
                            const float* __restrict__ Wuf, const float* __restrict__ Whf, const float* __restrict__ bf,
                            const float* __restrict__ Wug, const float* __restrict__ Whg, const float* __restrict__ bg,
                            const float* __restrict__ Wuo, const float* __restrict__ Who, const float* __restrict__ bo) {
    int idx = blockIdx.x * blockDim.x + threadIdx.x;
    int stride = gridDim.x * blockDim.x;
    for (int e = idx; e < ISZ * G4; e += stride) {
        int i = e / G4, j = e % G4, u = j >> 2, g = j & 3;
        const float* W = (g == 0) ? Wui : (g == 1) ? Wuf : (g == 2) ? Wug : Wuo;
        g_wu[e] = W[i * HSZ + u];
    }
    for (int e = idx; e < HSZ * G4; e += stride) {
        int k = e / G4, j = e % G4, u = j >> 2, g = j & 3;
        const float* W = (g == 0) ? Whi : (g == 1) ? Whf : (g == 2) ? Whg : Who;
        g_wh[e] = W[k * HSZ + u];
    }
    for (int e = idx; e < G4; e += stride) {
        int u = e >> 2, g = e & 3;
        const float* bb = (g == 0) ? bi : (g == 1) ? bf : (g == 2) ? bg : bo;
        g_bias[e] = bb[u];
    }
    for (int e = idx; e < BATCH * HSZ; e += stride) {
        g_h[0][e] = 0.0f;
        g_c[e] = 0.0f;
    }
}

// ---------------- phase 1: xu[t][b][:] = x[b][t][:] @ Wu_packed + bias -------
// GEMM M = SEQ*BATCH (row m -> t = m>>8, b = m&255), N = 2048, K = 256.
#define XBM 64
#define XBN 64
#define XBK 16

__global__ __launch_bounds__(256) void xu_kernel(const float* __restrict__ x) {
    __shared__ float As[XBK][XBM + 4];   // +4 pad: keeps 16B alignment for float4 reads
    __shared__ float Bs[XBK][XBN];

    int m0 = blockIdx.y * XBM;
    int n0 = blockIdx.x * XBN;
    int tid = threadIdx.x;
    int tx = tid & 15;          // 0..15 -> 4 cols each
    int ty = tid >> 4;          // 0..15 -> 4 rows each

    int arow = tid >> 2;        // 0..63
    int acol = (tid & 3) * 4;   // 0,4,8,12
    int brow = tid >> 4;        // 0..15
    int bcol = (tid & 15) * 4;  // 0..60

    int m = m0 + arow;
    int t = m >> 8;
    int b = m & 255;
    const float* aptr = x + (size_t)b * (SEQ * ISZ) + (size_t)t * ISZ;

    float acc[4][4] = {};

    for (int k0 = 0; k0 < ISZ; k0 += XBK) {
        float4 av = *(const float4*)(aptr + k0 + acol);
        As[acol + 0][arow] = av.x;
        As[acol + 1][arow] = av.y;
        As[acol + 2][arow] = av.z;
        As[acol + 3][arow] = av.w;
        *(float4*)&Bs[brow][bcol] =
            *(const float4*)(g_wu + (size_t)(k0 + brow) * G4 + n0 + bcol);
        __syncthreads();

#pragma unroll
        for (int kk = 0; kk < XBK; kk++) {
            float4 a4 = *(const float4*)&As[kk][ty * 4];
            float4 b4 = *(const float4*)&Bs[kk][tx * 4];
            float a[4] = {a4.x, a4.y, a4.z, a4.w};
            float bb[4] = {b4.x, b4.y, b4.z, b4.w};
#pragma unroll
            for (int r = 0; r < 4; r++)
#pragma unroll
                for (int c = 0; c < 4; c++)
                    acc[r][c] += a[r] * bb[c];
        }
        __syncthreads();
    }

#pragma unroll
    for (int r = 0; r < 4; r++) {
        int mm = m0 + ty * 4 + r;
        int nn = n0 + tx * 4;
        float4 ov;
        ov.x = acc[r][0] + g_bias[nn + 0];
        ov.y = acc[r][1] + g_bias[nn + 1];
        ov.z = acc[r][2] + g_bias[nn + 2];
        ov.w = acc[r][3] + g_bias[nn + 3];
        *(float4*)(g_xu + (size_t)mm * G4 + nn) = ov;
    }
}

// ---------------- phase 2: one timestep, GEMM + fused LSTM cell epilogue ----
// gates[b][j] = xu[t][b][j] + h_in[b][:] @ Wh_packed[:][j]
// Thread microtile = 4 batches x 4 cols, where the 4 cols are exactly the
// i,f,g,o gates of ONE unit -> cell update is register-local.
#define SBM 32
#define SBN 128
#define SBK 32

__global__ __launch_bounds__(256) void step_kernel(int t, float* __restrict__ final_out) {
    __shared__ float As[SBK][SBM + 4];
    __shared__ float Bs[SBK][SBN];

    const float* __restrict__ h_in = g_h[t & 1];
    float* __restrict__ h_out = (t == SEQ - 1) ? final_out : g_h[(t + 1) & 1];

    int b0 = blockIdx.y * SBM;
    int n0 = blockIdx.x * SBN;
    int tid = threadIdx.x;
    int tx = tid & 31;          // 0..31 -> 4 cols each (one unit)
    int ty = tid >> 5;          // 0..7  -> 4 rows each

    int arow = tid >> 3;        // 0..31
    int acol = (tid & 7) * 4;   // 0..28
    int brow = tid >> 5;        // 0..7 (x4 reps, +8)
    int bcol = (tid & 31) * 4;  // 0..124

    const float* aptr = h_in + (size_t)(b0 + arow) * HSZ;

    float acc[4][4] = {};

    for (int k0 = 0; k0 < HSZ; k0 += SBK) {
        float4 av = *(const float4*)(aptr + k0 + acol);
        As[acol + 0][arow] = av.x;
        As[acol + 1][arow] = av.y;
        As[acol + 2][arow] = av.z;
        As[acol + 3][arow] = av.w;
#pragma unroll
        for (int rep = 0; rep < 4; rep++) {
            int r = brow + rep * 8;
            *(float4*)&Bs[r][bcol] =
                *(const float4*)(g_wh + (size_t)(k0 + r) * G4 + n0 + bcol);
        }
        __syncthreads();

#pragma unroll
        for (int kk = 0; kk < SBK; kk++) {
            float4 a4 = *(const float4*)&As[kk][ty * 4];
            float4 b4 = *(const float4*)&Bs[kk][tx * 4];
            float a[4] = {a4.x, a4.y, a4.z, a4.w};
            float bb[4] = {b4.x, b4.y, b4.z, b4.w};
#pragma unroll
            for (int r = 0; r < 4; r++)
#pragma unroll
                for (int c = 0; c < 4; c++)
                    acc[r][c] += a[r] * bb[c];
        }
        __syncthreads();
    }

    // fused LSTM cell update (all 4 gates of unit u live in this thread)
    int u = (n0 >> 2) + tx;
#pragma unroll
    for (int r = 0; r < 4; r++) {
        int bidx = b0 + ty * 4 + r;
        float4 xv = *(const float4*)(g_xu + ((size_t)t * BATCH + bidx) * G4 + n0 + tx * 4);
        float pi = acc[r][0] + xv.x;
        float pf = acc[r][1] + xv.y;
        float pg = acc[r][2] + xv.z;
        float po = acc[r][3] + xv.w;

        float i_t = 1.0f / (1.0f + expf(-pi));
        float f_t = 1.0f / (1.0f + expf(-pf));
        float gg  = tanhf(pg);
        float o_t = 1.0f / (1.0f + expf(-po));

        size_t off = (size_t)bidx * HSZ + u;
        float c_new = f_t * g_c[off] + i_t * gg;
        g_c[off] = c_new;
        h_out[off] = o_t * tanhf(c_new);
    }
}

// ---------------- launch ----------------------------------------------------
extern "C" void kernel_launch(void* const* d_in, const int* in_sizes, int n_in,
                              void* d_out, int out_size) {
    const float* x   = (const float*)d_in[0];
    const float* Wui = (const float*)d_in[1];
    const float* Whi = (const float*)d_in[2];
    const float* bi  = (const float*)d_in[3];
    const float* Wuf = (const float*)d_in[4];
    const float* Whf = (const float*)d_in[5];
    const float* bf  = (const float*)d_in[6];
    const float* Wug = (const float*)d_in[7];
    const float* Whg = (const float*)d_in[8];
    const float* bg  = (const float*)d_in[9];
    const float* Wuo = (const float*)d_in[10];
    const float* Who = (const float*)d_in[11];
    const float* bo  = (const float*)d_in[12];
    float* out = (float*)d_out;

    pack_kernel<<<256, 256>>>(Wui, Whi, bi, Wuf, Whf, bf, Wug, Whg, bg, Wuo, Who, bo);

    dim3 xu_grid(G4 / XBN, (SEQ * BATCH) / XBM);   // (32, 2048)
    xu_kernel<<<xu_grid, 256>>>(x);

    dim3 step_grid(G4 / SBN, BATCH / SBM);         // (16, 8) = 128 blocks
    for (int t = 0; t < SEQ; t++) {
        step_kernel<<<step_grid, 256>>>(t, out);
    }
}

// round 3
// speedup vs baseline: 1.1031x; 1.1031x over previous
#include <cuda_runtime.h>
#include <math.h>

#define BATCH 256
#define SEQ   512
#define ISZ   256
#define HSZ   512
#define G4    2048   // 4*HSZ, gate-interleaved: col j = u*4 + g, g in {i,f,g,o}

// ---------------- device scratch (allocation-free) ----------------
__device__ float g_xu[(size_t)SEQ * BATCH * G4];  // 1 GiB: xu[t][b][j]
__device__ float g_wu[ISZ * G4];                  // packed W_u  [I][4H interleaved]
__device__ float g_wh[HSZ * G4];                  // packed W_h  [H][4H interleaved]
__device__ float g_bias[G4];
__device__ float g_h[2][BATCH * HSZ];             // double-buffered hidden state
__device__ unsigned g_arrive;                     // grid-sync counter

// ---------------- f32x2 helpers (sm_103a packed fp32) ----------------
__device__ __forceinline__ unsigned long long fma2(unsigned long long a,
                                                   unsigned long long b,
                                                   unsigned long long c) {
    unsigned long long d;
    asm("fma.rn.f32x2 %0, %1, %2, %3;" : "=l"(d) : "l"(a), "l"(b), "l"(c));
    return d;
}
__device__ __forceinline__ unsigned long long dup2(float x) {
    unsigned long long d;
    asm("mov.b64 %0, {%1, %1};" : "=l"(d) : "f"(x));
    return d;
}
__device__ __forceinline__ float2 unpk(unsigned long long v) {
    float2 r;
    asm("mov.b64 {%0, %1}, %2;" : "=f"(r.x), "=f"(r.y) : "l"(v));
    return r;
}

__device__ __forceinline__ float fsig(float x)  { return 1.0f / (1.0f + __expf(-x)); }
__device__ __forceinline__ float ftanh(float x) { return 2.0f / (1.0f + __expf(-2.0f * x)) - 1.0f; }

// release-add / acquire-load pair for the grid barrier
__device__ __forceinline__ void arrive_release(unsigned* p) {
    asm volatile("red.release.gpu.global.add.u32 [%0], 1;" :: "l"(p) : "memory");
}
__device__ __forceinline__ unsigned poll_acquire(const unsigned* p) {
    unsigned v;
    asm volatile("ld.acquire.gpu.global.u32 %0, [%1];" : "=r"(v) : "l"(p) : "memory");
    return v;
}

// ---------------- pack weights + init state + reset sync ----------------
__global__ void pack_kernel(const float* __restrict__ Wui, const float* __restrict__ Whi, const float* __restrict__ bi,
                            const float* __restrict__ Wuf, const float* __restrict__ Whf, const float* __restrict__ bf,
                            const float* __restrict__ Wug, const float* __restrict__ Whg, const float* __restrict__ bg,
                            const float* __restrict__ Wuo, const float* __restrict__ Who, const float* __restrict__ bo) {
    int idx = blockIdx.x * blockDim.x + threadIdx.x;
    int stride = gridDim.x * blockDim.x;
    if (idx == 0) g_arrive = 0u;
    for (int e = idx; e < ISZ * G4; e += stride) {
        int i = e / G4, j = e % G4, u = j >> 2, g = j & 3;
        const float* W = (g == 0) ? Wui : (g == 1) ? Wuf : (g == 2) ? Wug : Wuo;
        g_wu[e] = W[i * HSZ + u];
    }
    for (int e = idx; e < HSZ * G4; e += stride) {
        int k = e / G4, j = e % G4, u = j >> 2, g = j & 3;
        const float* W = (g == 0) ? Whi : (g == 1) ? Whf : (g == 2) ? Whg : Who;
        g_wh[e] = W[k * HSZ + u];
    }
    for (int e = idx; e < G4; e += stride) {
        int u = e >> 2, g = e & 3;
        const float* bb = (g == 0) ? bi : (g == 1) ? bf : (g == 2) ? bg : bo;
        g_bias[e] = bb[u];
    }
    for (int e = idx; e < BATCH * HSZ; e += stride) {
        g_h[0][e] = 0.0f;
    }
}

// ---------------- phase 1: xu = x @ Wu_packed + bias (f32x2 FMAs) ------------
#define XBM 64
#define XBN 64
#define XBK 16

__global__ __launch_bounds__(256) void xu_kernel(const float* __restrict__ x) {
    __shared__ float As[XBK][XBM + 4];
    __shared__ float Bs[XBK][XBN];

    int m0 = blockIdx.y * XBM;
    int n0 = blockIdx.x * XBN;
    int tid = threadIdx.x;
    int tx = tid & 15;
    int ty = tid >> 4;

    int arow = tid >> 2;
    int acol = (tid & 3) * 4;
    int brow = tid >> 4;
    int bcol = (tid & 15) * 4;

    int m = m0 + arow;
    int t = m >> 8;
    int b = m & 255;
    const float* aptr = x + (size_t)b * (SEQ * ISZ) + (size_t)t * ISZ;

    unsigned long long acc[2][4] = {};  // [rowpair][col], lanes = 2 adjacent rows

    for (int k0 = 0; k0 < ISZ; k0 += XBK) {
        float4 av = *(const float4*)(aptr + k0 + acol);
        As[acol + 0][arow] = av.x;
        As[acol + 1][arow] = av.y;
        As[acol + 2][arow] = av.z;
        As[acol + 3][arow] = av.w;
        *(float4*)&Bs[brow][bcol] =
            *(const float4*)(g_wu + (size_t)(k0 + brow) * G4 + n0 + bcol);
        __syncthreads();

#pragma unroll
        for (int kk = 0; kk < XBK; kk++) {
            ulonglong2 a2 = *(const ulonglong2*)&As[kk][ty * 4];
            float4 b4 = *(const float4*)&Bs[kk][tx * 4];
            unsigned long long bd0 = dup2(b4.x), bd1 = dup2(b4.y);
            unsigned long long bd2 = dup2(b4.z), bd3 = dup2(b4.w);
            acc[0][0] = fma2(a2.x, bd0, acc[0][0]);
            acc[1][0] = fma2(a2.y, bd0, acc[1][0]);
            acc[0][1] = fma2(a2.x, bd1, acc[0][1]);
            acc[1][1] = fma2(a2.y, bd1, acc[1][1]);
            acc[0][2] = fma2(a2.x, bd2, acc[0][2]);
            acc[1][2] = fma2(a2.y, bd2, acc[1][2]);
            acc[0][3] = fma2(a2.x, bd3, acc[0][3]);
            acc[1][3] = fma2(a2.y, bd3, acc[1][3]);
        }
        __syncthreads();
    }

    int nn = n0 + tx * 4;
    float4 bias4 = *(const float4*)(g_bias + nn);
#pragma unroll
    for (int rp = 0; rp < 2; rp++) {
        float2 v0 = unpk(acc[rp][0]);
        float2 v1 = unpk(acc[rp][1]);
        float2 v2 = unpk(acc[rp][2]);
        float2 v3 = unpk(acc[rp][3]);
        int mm = m0 + ty * 4 + rp * 2;
        float4 oa = {v0.x + bias4.x, v1.x + bias4.y, v2.x + bias4.z, v3.x + bias4.w};
        float4 ob = {v0.y + bias4.x, v1.y + bias4.y, v2.y + bias4.z, v3.y + bias4.w};
        *(float4*)(g_xu + (size_t)mm * G4 + nn) = oa;
        *(float4*)(g_xu + (size_t)(mm + 1) * G4 + nn) = ob;
    }
}

// ---------------- phase 2: PERSISTENT kernel, all 512 steps ------------------
// 128 blocks x 256 threads, guaranteed 1 block/SM co-residency (136.5KB smem).
// Each block owns a 64-batch x 64-col tile; W_h slice staged in smem ONCE.
// Cell state c lives in registers. Grid sync between steps: release-atomic
// arrival + acquire-load poll on a monotonic counter.
#define PBLKS 128
#define PN 64          // cols per block (16 units)
#define PM 64          // batches per block
#define PK 32          // k chunk
#define ASTRIDE (PM + 4)

#define P_SMEM_FLOATS (HSZ * PN + PK * ASTRIDE)
#define P_SMEM_BYTES  (P_SMEM_FLOATS * 4)

extern __shared__ float s_mem[];

__global__ __launch_bounds__(256, 1) void lstm_persistent(float* __restrict__ out) {
    float* Whs = s_mem;                 // [512][64]
    float* As  = s_mem + HSZ * PN;      // [PK][ASTRIDE] transposed h chunk

    int tid = threadIdx.x;
    int bx = blockIdx.x & 31;           // 32 n-tiles
    int by = blockIdx.x >> 5;           // 4 batch-tiles
    int n0 = bx * PN;
    int b0 = by * PM;
    int tx = tid & 15;                  // unit within tile
    int ty = tid >> 4;                  // batch group

    // ---- stage W_h slice into smem once ----
    for (int i = tid; i < HSZ * PN / 4; i += 256) {
        int k = i >> 4;
        int c4 = i & 15;
        *(float4*)&Whs[k * PN + c4 * 4] =
            *(const float4*)&g_wh[(size_t)k * G4 + n0 + c4 * 4];
    }
    __syncthreads();

    // per-thread cell state: 4 batches x 1 unit
    float creg[4] = {0.f, 0.f, 0.f, 0.f};
    int u = (n0 >> 2) + tx;

    // A-prefetch mapping: each thread loads 8 consecutive k-floats of one row
    int prow = tid >> 2;                // 0..63
    int pkof = (tid & 3) * 8;           // 0,8,16,24

    for (int t = 0; t < SEQ; t++) {
        const float* __restrict__ h_in = g_h[t & 1];
        const float* aptr = h_in + (size_t)(b0 + prow) * HSZ + pkof;

        unsigned long long acc[2][4] = {};

        float4 pa = __ldcg((const float4*)(aptr + 0));
        float4 pb = __ldcg((const float4*)(aptr + 4));

        for (int k0 = 0; k0 < HSZ; k0 += PK) {
            // store prefetched chunk (transposed)
            As[(pkof + 0) * ASTRIDE + prow] = pa.x;
            As[(pkof + 1) * ASTRIDE + prow] = pa.y;
            As[(pkof + 2) * ASTRIDE + prow] = pa.z;
            As[(pkof + 3) * ASTRIDE + prow] = pa.w;
            As[(pkof + 4) * ASTRIDE + prow] = pb.x;
            As[(pkof + 5) * ASTRIDE + prow] = pb.y;
            As[(pkof + 6) * ASTRIDE + prow] = pb.z;
            As[(pkof + 7) * ASTRIDE + prow] = pb.w;
            __syncthreads();

            if (k0 + PK < HSZ) {
                pa = __ldcg((const float4*)(aptr + k0 + PK));
                pb = __ldcg((const float4*)(aptr + k0 + PK + 4));
            }

            const float* wrow = &Whs[k0 * PN + tx * 4];
#pragma unroll
            for (int kk = 0; kk < PK; kk++) {
                ulonglong2 a2 = *(const ulonglong2*)&As[kk * ASTRIDE + ty * 4];
                float4 b4 = *(const float4*)(wrow + kk * PN);
                unsigned long long bd0 = dup2(b4.x), bd1 = dup2(b4.y);
                unsigned long long bd2 = dup2(b4.z), bd3 = dup2(b4.w);
                acc[0][0] = fma2(a2.x, bd0, acc[0][0]);
                acc[1][0] = fma2(a2.y, bd0, acc[1][0]);
                acc[0][1] = fma2(a2.x, bd1, acc[0][1]);
                acc[1][1] = fma2(a2.y, bd1, acc[1][1]);
                acc[0][2] = fma2(a2.x, bd2, acc[0][2]);
                acc[1][2] = fma2(a2.y, bd2, acc[1][2]);
                acc[0][3] = fma2(a2.x, bd3, acc[0][3]);
                acc[1][3] = fma2(a2.y, bd3, acc[1][3]);
            }
            __syncthreads();
        }

        // ---- fused LSTM cell epilogue (gates are register-local) ----
        float* __restrict__ h_out = (t == SEQ - 1) ? out : g_h[(t + 1) & 1];
        const float* xubase = g_xu + ((size_t)t * BATCH) * G4 + n0 + tx * 4;

#pragma unroll
        for (int rp = 0; rp < 2; rp++) {
            float2 gi = unpk(acc[rp][0]);
            float2 gf = unpk(acc[rp][1]);
            float2 gg = unpk(acc[rp][2]);
            float2 go = unpk(acc[rp][3]);
#pragma unroll
            for (int h = 0; h < 2; h++) {
                int ri = rp * 2 + h;
                int b = b0 + ty * 4 + ri;
                float4 xv = *(const float4*)(xubase + (size_t)b * G4);
                float pi = (h ? gi.y : gi.x) + xv.x;
                float pf = (h ? gf.y : gf.x) + xv.y;
                float pg = (h ? gg.y : gg.x) + xv.z;
                float po = (h ? go.y : go.x) + xv.w;

                float it = fsig(pi);
                float ft = fsig(pf);
                float gt = ftanh(pg);
                float ot = fsig(po);

                float cnew = ft * creg[ri] + it * gt;
                creg[ri] = cnew;
                h_out[(size_t)b * HSZ + u] = ot * ftanh(cnew);
            }
        }

        // ---- grid-wide sync (skip after last step) ----
        if (t < SEQ - 1) {
            __syncthreads();            // all threads done with step t
            if (tid == 0) {
                arrive_release(&g_arrive);          // publishes our writes
                unsigned target = (unsigned)(t + 1) * (unsigned)PBLKS;
                while (poll_acquire(&g_arrive) < target) {
                    __nanosleep(64);
                }
            }
            __syncthreads();            // fans the acquire out to the block
        }
    }
}

// ---------------- launch ----------------------------------------------------
extern "C" void kernel_launch(void* const* d_in, const int* in_sizes, int n_in,
                              void* d_out, int out_size) {
    const float* x   = (const float*)d_in[0];
    const float* Wui = (const float*)d_in[1];
    const float* Whi = (const float*)d_in[2];
    const float* bi  = (const float*)d_in[3];
    const float* Wuf = (const float*)d_in[4];
    const float* Whf = (const float*)d_in[5];
    const float* bf  = (const float*)d_in[6];
    const float* Wug = (const float*)d_in[7];
    const float* Whg = (const float*)d_in[8];
    const float* bg  = (const float*)d_in[9];
    const float* Wuo = (const float*)d_in[10];
    const float* Who = (const float*)d_in[11];
    const float* bo  = (const float*)d_in[12];
    float* out = (float*)d_out;

    cudaFuncSetAttribute(lstm_persistent,
                         cudaFuncAttributeMaxDynamicSharedMemorySize, P_SMEM_BYTES);

    pack_kernel<<<256, 256>>>(Wui, Whi, bi, Wuf, Whf, bf, Wug, Whg, bg, Wuo, Who, bo);

    dim3 xu_grid(G4 / XBN, (SEQ * BATCH) / XBM);   // (32, 2048)
    xu_kernel<<<xu_grid, 256>>>(x);

    lstm_persistent<<<PBLKS, 256, P_SMEM_BYTES>>>(out);
}